// round 3
// baseline (speedup 1.0000x reference)
#include <cuda_runtime.h>
#include <math.h>

#define BB 2
#define SS 2048
#define DD 1024
#define HH 16
#define HD 64
#define NBLK 128   // SS / 16

#define MT 128
#define NT 128
#define KT 8

// Scratch: q,k,v in [b][h][s][d] layout for attention-friendly access.
__device__ float g_q[BB*HH*SS*HD];
__device__ float g_k[BB*HH*SS*HD];
__device__ float g_v[BB*HH*SS*HD];

// ---------------------------------------------------------------------------
// QKV projection: out[b][h][s][d] = sum_k x[b*S+s][k] * W[k][h*64+d] + bias
// 128x128 tile, 256 threads, KT=8, per-thread 2x2 fragments of 4x4.
// ---------------------------------------------------------------------------
__global__ void __launch_bounds__(256, 2)
qkv_gemm_kernel(const float* __restrict__ x,
                const float* __restrict__ W,
                const float* __restrict__ bias,
                int which) {
    float* out = (which == 0) ? g_q : (which == 1) ? g_k : g_v;

    __shared__ float As[KT][MT + 4];   // transposed A tile, padded
    __shared__ float Bs[KT][NT + 4];

    const int tid = threadIdx.x;          // 0..255
    const int tc  = tid & 15;             // 0..15 -> cols tc*4 and 64+tc*4
    const int tr  = tid >> 4;             // 0..15 -> rows tr*4 and 64+tr*4
    const int row0 = blockIdx.x * MT;     // over B*S = 4096
    const int col0 = blockIdx.y * NT;     // over D = 1024

    // A-load mapping: 1024 floats = 256 float4; m = tid/2, q = tid&1
    const int am = tid >> 1;
    const int aq = (tid & 1) * 4;
    // B-load mapping: kk = tid/32, c = (tid%32)*4
    const int bk = tid >> 5;
    const int bc = (tid & 31) * 4;

    float acc[2][2][4][4] = {};

    for (int k0 = 0; k0 < DD; k0 += KT) {
        // Stage A (128 x 8) transposed
        float4 xa = *reinterpret_cast<const float4*>(
            &x[(size_t)(row0 + am) * DD + k0 + aq]);
        As[aq + 0][am] = xa.x;
        As[aq + 1][am] = xa.y;
        As[aq + 2][am] = xa.z;
        As[aq + 3][am] = xa.w;
        // Stage B (8 x 128) direct
        *reinterpret_cast<float4*>(&Bs[bk][bc]) =
            *reinterpret_cast<const float4*>(&W[(size_t)(k0 + bk) * DD + col0 + bc]);
        __syncthreads();

        #pragma unroll
        for (int kk = 0; kk < KT; kk++) {
            float4 a0 = *reinterpret_cast<const float4*>(&As[kk][tr * 4]);
            float4 a1 = *reinterpret_cast<const float4*>(&As[kk][64 + tr * 4]);
            float4 b0 = *reinterpret_cast<const float4*>(&Bs[kk][tc * 4]);
            float4 b1 = *reinterpret_cast<const float4*>(&Bs[kk][64 + tc * 4]);
            float av[2][4] = {{a0.x, a0.y, a0.z, a0.w}, {a1.x, a1.y, a1.z, a1.w}};
            float bv[2][4] = {{b0.x, b0.y, b0.z, b0.w}, {b1.x, b1.y, b1.z, b1.w}};
            #pragma unroll
            for (int ri = 0; ri < 2; ri++)
                #pragma unroll
                for (int ci = 0; ci < 2; ci++)
                    #pragma unroll
                    for (int i = 0; i < 4; i++)
                        #pragma unroll
                        for (int j = 0; j < 4; j++)
                            acc[ri][ci][i][j] =
                                fmaf(av[ri][i], bv[ci][j], acc[ri][ci][i][j]);
        }
        __syncthreads();
    }

    // Epilogue: +bias, scatter to [b][h][s][d]. Each (ri,ci,i) row of 4 cols is
    // contiguous in d (fragment stays inside one head since NT=128=2 heads).
    #pragma unroll
    for (int ri = 0; ri < 2; ri++) {
        #pragma unroll
        for (int i = 0; i < 4; i++) {
            int row = row0 + ri * 64 + tr * 4 + i;   // = b*S + s
            int b_ = row >> 11;                      // /2048
            int s_ = row & 2047;
            #pragma unroll
            for (int ci = 0; ci < 2; ci++) {
                int col = col0 + ci * 64 + tc * 4;   // head-aligned groups of 4
                int h_ = col >> 6;
                int d_ = col & 63;
                float4 bb = *reinterpret_cast<const float4*>(&bias[col]);
                float4 r;
                r.x = acc[ri][ci][i][0] + bb.x;
                r.y = acc[ri][ci][i][1] + bb.y;
                r.z = acc[ri][ci][i][2] + bb.z;
                r.w = acc[ri][ci][i][3] + bb.w;
                *reinterpret_cast<float4*>(
                    &out[((size_t)((b_ * HH + h_) * SS) + s_) * HD + d_]) = r;
            }
        }
    }
}

// ---------------------------------------------------------------------------
// Block-sparse attention. Grid: (q_block, head, batch). 512 threads = 16 warps;
// warp w owns query row w of the 16-row q-block. Online softmax over the
// allowed key-block list (shared by all queries in the q-block):
//   globals: kb = 4g+3 for g in [0, qb>>2)
//   window : kb = (qb & ~3) + t for t in [0, qb&3]
// Mask is block-causal => the diagonal block is FULLY allowed (no token mask).
// ---------------------------------------------------------------------------
__global__ void sparse_attn_kernel(const float* __restrict__ kpm,
                                   float* __restrict__ out) {
    const int qb = blockIdx.x;
    const int h  = blockIdx.y;
    const int b  = blockIdx.z;

    __shared__ float ks[16][64];
    __shared__ float vs[16][64];
    __shared__ float kpms[16];

    const int tid = threadIdx.x;
    const int w   = tid >> 5;   // query row within block (warp id)
    const int l   = tid & 31;   // lane

    const size_t head_base = (size_t)(b * HH + h) * SS * HD;
    const float* qp = g_q + head_base + (size_t)(qb * 16 + w) * HD;
    const float q0 = qp[l];
    const float q1 = qp[l + 32];

    float m = -INFINITY, lsum = 0.f, o0 = 0.f, o1 = 0.f;
    const float scale = 0.125f;  // 64^-0.5

    const int nglob = qb >> 2;
    const int nwin  = (qb & 3) + 1;
    const int nkb   = nglob + nwin;

    for (int t = 0; t < nkb; t++) {
        const int kb = (t < nglob) ? (t * 4 + 3) : ((qb & ~3) + (t - nglob));

        __syncthreads();
        // Cooperative stage of K,V block (16x64 each)
        for (int idx = tid; idx < 1024; idx += 512) {
            int r = idx >> 6, d = idx & 63;
            size_t gi = head_base + (size_t)(kb * 16 + r) * HD + d;
            ks[r][d] = g_k[gi];
            vs[r][d] = g_v[gi];
        }
        if (tid < 16) kpms[tid] = kpm[b * SS + kb * 16 + tid];
        __syncthreads();

        // 16 scores per query via warp butterfly reduction (all lanes get s_j)
        float sj[16];
        float bmax = -INFINITY;
        #pragma unroll
        for (int j = 0; j < 16; j++) {
            float p = q0 * ks[j][l] + q1 * ks[j][l + 32];
            p += __shfl_xor_sync(0xffffffffu, p, 16);
            p += __shfl_xor_sync(0xffffffffu, p, 8);
            p += __shfl_xor_sync(0xffffffffu, p, 4);
            p += __shfl_xor_sync(0xffffffffu, p, 2);
            p += __shfl_xor_sync(0xffffffffu, p, 1);
            sj[j] = p * scale + kpms[j];
            bmax = fmaxf(bmax, sj[j]);
        }

        const float newm = fmaxf(m, bmax);
        const float alpha = (m == -INFINITY) ? 0.f : __expf(m - newm);
        lsum *= alpha; o0 *= alpha; o1 *= alpha;

        #pragma unroll
        for (int j = 0; j < 16; j++) {
            float pj = __expf(sj[j] - newm);
            lsum += pj;
            o0 = fmaf(pj, vs[j][l],      o0);
            o1 = fmaf(pj, vs[j][l + 32], o1);
        }
        m = newm;
    }

    const float inv = 1.f / lsum;
    const int srow = qb * 16 + w;
    float* op = out + (size_t)(b * SS + srow) * DD + h * HD;
    op[l]      = o0 * inv;
    op[l + 32] = o1 * inv;
}

// ---------------------------------------------------------------------------
// Launch
// ---------------------------------------------------------------------------
extern "C" void kernel_launch(void* const* d_in, const int* in_sizes, int n_in,
                              void* d_out, int out_size) {
    const float* x   = (const float*)d_in[0];
    const float* kpm = (const float*)d_in[1];
    const float* Wq  = (const float*)d_in[2];
    const float* bq  = (const float*)d_in[3];
    const float* Wk  = (const float*)d_in[4];
    const float* bk  = (const float*)d_in[5];
    const float* Wv  = (const float*)d_in[6];
    const float* bv  = (const float*)d_in[7];
    float* out = (float*)d_out;

    dim3 ggrid(32, 8);   // 4096/128 row tiles x 1024/128 col tiles
    qkv_gemm_kernel<<<ggrid, 256>>>(x, Wq, bq, 0);
    qkv_gemm_kernel<<<ggrid, 256>>>(x, Wk, bk, 1);
    qkv_gemm_kernel<<<ggrid, 256>>>(x, Wv, bv, 2);

    dim3 agrid(NBLK, HH, BB);
    sparse_attn_kernel<<<agrid, 512>>>(kpm, out);
}

// round 4
// speedup vs baseline: 1.6838x; 1.6838x over previous
#include <cuda_runtime.h>
#include <math.h>

#define BB 2
#define SS 2048
#define DD 1024
#define HH 16
#define HD 64

#define MT 128
#define NT 128
#define KT 8

// Scratch: q,k,v in [b][h][s][d] layout for attention-friendly access.
__device__ float g_q[BB*HH*SS*HD];
__device__ float g_k[BB*HH*SS*HD];
__device__ float g_v[BB*HH*SS*HD];

// ---------------------------------------------------------------------------
// QKV projection: out[b][h][s][d] = sum_k x[b*S+s][k] * W[k][h*64+d] + bias
// 128x128 tile, 256 threads, KT=8, per-thread 2x2 fragments of 4x4.
// ---------------------------------------------------------------------------
__global__ void __launch_bounds__(256, 2)
qkv_gemm_kernel(const float* __restrict__ x,
                const float* __restrict__ W,
                const float* __restrict__ bias,
                int which) {
    float* out = (which == 0) ? g_q : (which == 1) ? g_k : g_v;

    __shared__ float As[KT][MT + 4];   // transposed A tile, padded
    __shared__ float Bs[KT][NT + 4];

    const int tid = threadIdx.x;
    const int tc  = tid & 15;
    const int tr  = tid >> 4;
    const int row0 = blockIdx.x * MT;
    const int col0 = blockIdx.y * NT;

    const int am = tid >> 1;
    const int aq = (tid & 1) * 4;
    const int bk = tid >> 5;
    const int bc = (tid & 31) * 4;

    float acc[2][2][4][4] = {};

    for (int k0 = 0; k0 < DD; k0 += KT) {
        float4 xa = *reinterpret_cast<const float4*>(
            &x[(size_t)(row0 + am) * DD + k0 + aq]);
        As[aq + 0][am] = xa.x;
        As[aq + 1][am] = xa.y;
        As[aq + 2][am] = xa.z;
        As[aq + 3][am] = xa.w;
        *reinterpret_cast<float4*>(&Bs[bk][bc]) =
            *reinterpret_cast<const float4*>(&W[(size_t)(k0 + bk) * DD + col0 + bc]);
        __syncthreads();

        #pragma unroll
        for (int kk = 0; kk < KT; kk++) {
            float4 a0 = *reinterpret_cast<const float4*>(&As[kk][tr * 4]);
            float4 a1 = *reinterpret_cast<const float4*>(&As[kk][64 + tr * 4]);
            float4 b0 = *reinterpret_cast<const float4*>(&Bs[kk][tc * 4]);
            float4 b1 = *reinterpret_cast<const float4*>(&Bs[kk][64 + tc * 4]);
            float av[2][4] = {{a0.x, a0.y, a0.z, a0.w}, {a1.x, a1.y, a1.z, a1.w}};
            float bv[2][4] = {{b0.x, b0.y, b0.z, b0.w}, {b1.x, b1.y, b1.z, b1.w}};
            #pragma unroll
            for (int ri = 0; ri < 2; ri++)
                #pragma unroll
                for (int ci = 0; ci < 2; ci++)
                    #pragma unroll
                    for (int i = 0; i < 4; i++)
                        #pragma unroll
                        for (int j = 0; j < 4; j++)
                            acc[ri][ci][i][j] =
                                fmaf(av[ri][i], bv[ci][j], acc[ri][ci][i][j]);
        }
        __syncthreads();
    }

    #pragma unroll
    for (int ri = 0; ri < 2; ri++) {
        #pragma unroll
        for (int i = 0; i < 4; i++) {
            int row = row0 + ri * 64 + tr * 4 + i;
            int b_ = row >> 11;
            int s_ = row & 2047;
            #pragma unroll
            for (int ci = 0; ci < 2; ci++) {
                int col = col0 + ci * 64 + tc * 4;
                int h_ = col >> 6;
                int d_ = col & 63;
                float4 bb = *reinterpret_cast<const float4*>(&bias[col]);
                float4 r;
                r.x = acc[ri][ci][i][0] + bb.x;
                r.y = acc[ri][ci][i][1] + bb.y;
                r.z = acc[ri][ci][i][2] + bb.z;
                r.w = acc[ri][ci][i][3] + bb.w;
                *reinterpret_cast<float4*>(
                    &out[((size_t)((b_ * HH + h_) * SS) + s_) * HD + d_]) = r;
            }
        }
    }
}

// ---------------------------------------------------------------------------
// Flash-style block-sparse attention over 64-query windows.
// Grid: (window 0..31, head, batch). 256 threads = (ty 0..15) x (tx 0..15).
// Each thread owns a 4x4 score fragment (rows ty*4.., cols tx*4..) and a
// 4x4 output fragment (rows ty*4.., dims tx*4..).
//
// Key-block schedule for window w (queries 64w..64w+63):
//   global tiles: it = 0..ceil(w/4)-1, keys kb = 4*(4*it+g)+3 (g=0..3, valid
//                 while 4*it+g < w); no intra-tile mask (all strictly causal).
//   window tile : keys = blocks 4w..4w+3; block-causal mask (kc>>4) <= (qr>>4),
//                 which is thread-uniform: (tx>>2) <= (ty>>2).
//
// Dynamic smem (52.5 KB):
//   Qst [64d][68]  : Q transposed (d-major)       -- staged once
//   KP  [64][68]   : K transposed (d-major) during S-GEMM, then reused as
//                    P (q-major rows) for the PV GEMM
//   Vs  [64k][68]  : V natural (k-major rows)
//   kpms[64]       : additive key-padding-mask values (-inf for invalid keys)
// ---------------------------------------------------------------------------
#define PAD 68
#define SM_Q 0
#define SM_KP (64*PAD)
#define SM_V  (2*64*PAD)
#define SM_KPM (3*64*PAD)
#define SM_FLOATS (3*64*PAD + 64)

__global__ void __launch_bounds__(256)
sparse_attn_kernel(const float* __restrict__ kpm, float* __restrict__ out) {
    extern __shared__ float sm[];
    float* Qst  = sm + SM_Q;
    float* KP   = sm + SM_KP;
    float* Vs   = sm + SM_V;
    float* kpms = sm + SM_KPM;

    const int w = blockIdx.x;
    const int h = blockIdx.y;
    const int b = blockIdx.z;

    const int tid = threadIdx.x;
    const int tx  = tid & 15;
    const int ty  = tid >> 4;

    const size_t head_base = (size_t)(b * HH + h) * SS * HD;

    // ---- Stage Q (64 x 64) transposed: Qst[d][q] ----
    {
        const int r  = tid >> 2;             // query row 0..63
        const int dq = (tid & 3) << 4;       // d offset 0,16,32,48
        const float* qrow = g_q + head_base + (size_t)(w * 64 + r) * HD;
        #pragma unroll
        for (int u = 0; u < 4; u++) {
            float4 qv = *reinterpret_cast<const float4*>(&qrow[dq + u * 4]);
            Qst[(dq + u * 4 + 0) * PAD + r] = qv.x;
            Qst[(dq + u * 4 + 1) * PAD + r] = qv.y;
            Qst[(dq + u * 4 + 2) * PAD + r] = qv.z;
            Qst[(dq + u * 4 + 3) * PAD + r] = qv.w;
        }
    }

    float m[4], l[4], o[4][4];
    #pragma unroll
    for (int i = 0; i < 4; i++) {
        m[i] = -1e30f; l[i] = 0.f;
        #pragma unroll
        for (int j = 0; j < 4; j++) o[i][j] = 0.f;
    }

    const float scale = 0.125f;  // 64^-0.5
    const int nkt = (w + 3) >> 2;        // global tiles
    const bool winMasked = (tx >> 2) > (ty >> 2);

    for (int it = 0; it <= nkt; it++) {
        const bool isWin = (it == nkt);

        __syncthreads();   // prev-iter P/V consumers done before restage

        // ---- Stage K (transposed) + V (natural) + kpms for this tile ----
        {
            const int r  = tid >> 2;
            const int dq = (tid & 3) << 4;
            int kb; bool valid;
            if (isWin) { kb = 4 * w + (r >> 4); valid = true; }
            else {
                int g = it * 4 + (r >> 4);
                valid = (g < w);
                kb = 4 * g + 3;
            }
            const float* krow = g_k + head_base + (size_t)(kb * 16 + (r & 15)) * HD;
            const float* vrow = g_v + head_base + (size_t)(kb * 16 + (r & 15)) * HD;
            const float4 z4 = make_float4(0.f, 0.f, 0.f, 0.f);
            #pragma unroll
            for (int u = 0; u < 4; u++) {
                float4 kv = valid ? *reinterpret_cast<const float4*>(&krow[dq + u * 4]) : z4;
                KP[(dq + u * 4 + 0) * PAD + r] = kv.x;
                KP[(dq + u * 4 + 1) * PAD + r] = kv.y;
                KP[(dq + u * 4 + 2) * PAD + r] = kv.z;
                KP[(dq + u * 4 + 3) * PAD + r] = kv.w;
                float4 vv = valid ? *reinterpret_cast<const float4*>(&vrow[dq + u * 4]) : z4;
                *reinterpret_cast<float4*>(&Vs[r * PAD + dq + u * 4]) = vv;
            }
            if (tid < 64) {
                int kk = tid;
                int kb2; bool v2;
                if (isWin) { kb2 = 4 * w + (kk >> 4); v2 = true; }
                else {
                    int g2 = it * 4 + (kk >> 4);
                    v2 = (g2 < w);
                    kb2 = 4 * g2 + 3;
                }
                kpms[kk] = v2 ? kpm[b * SS + kb2 * 16 + (kk & 15)] : -INFINITY;
            }
        }
        __syncthreads();

        // ---- S = Q K^T : 4x4 fragment per thread ----
        float s[4][4] = {};
        #pragma unroll 8
        for (int d = 0; d < 64; d++) {
            float4 a = *reinterpret_cast<const float4*>(&Qst[d * PAD + ty * 4]);
            float4 bf = *reinterpret_cast<const float4*>(&KP[d * PAD + tx * 4]);
            float av[4] = {a.x, a.y, a.z, a.w};
            float bv[4] = {bf.x, bf.y, bf.z, bf.w};
            #pragma unroll
            for (int i = 0; i < 4; i++)
                #pragma unroll
                for (int j = 0; j < 4; j++)
                    s[i][j] = fmaf(av[i], bv[j], s[i][j]);
        }

        // scale + kpm + mask
        #pragma unroll
        for (int i = 0; i < 4; i++)
            #pragma unroll
            for (int j = 0; j < 4; j++) {
                float val = s[i][j] * scale + kpms[tx * 4 + j];
                if (isWin && winMasked) val = -INFINITY;
                s[i][j] = val;
            }

        // ---- online softmax update ----
        float rm[4], rs[4], alpha[4];
        #pragma unroll
        for (int i = 0; i < 4; i++) {
            rm[i] = fmaxf(fmaxf(s[i][0], s[i][1]), fmaxf(s[i][2], s[i][3]));
            #pragma unroll
            for (int off = 1; off < 16; off <<= 1)
                rm[i] = fmaxf(rm[i], __shfl_xor_sync(0xffffffffu, rm[i], off));
        }
        #pragma unroll
        for (int i = 0; i < 4; i++) {
            float newm = fmaxf(m[i], rm[i]);
            alpha[i] = __expf(m[i] - newm);
            m[i] = newm;
            float acc = 0.f;
            #pragma unroll
            for (int j = 0; j < 4; j++) {
                float p = __expf(s[i][j] - newm);
                s[i][j] = p;
                acc += p;
            }
            rs[i] = acc;
            #pragma unroll
            for (int off = 1; off < 16; off <<= 1)
                rs[i] += __shfl_xor_sync(0xffffffffu, rs[i], off);
            l[i] = l[i] * alpha[i] + rs[i];
            #pragma unroll
            for (int j = 0; j < 4; j++) o[i][j] *= alpha[i];
        }

        __syncthreads();   // all S-GEMM reads of KP (K) done

        // ---- write P into KP as [q][k] ----
        #pragma unroll
        for (int i = 0; i < 4; i++)
            *reinterpret_cast<float4*>(&KP[(ty * 4 + i) * PAD + tx * 4]) =
                make_float4(s[i][0], s[i][1], s[i][2], s[i][3]);
        __syncthreads();

        // ---- O += P V : thread fragment rows ty*4.., dims tx*4.. ----
        #pragma unroll 8
        for (int k = 0; k < 64; k++) {
            float4 vv = *reinterpret_cast<const float4*>(&Vs[k * PAD + tx * 4]);
            float vf[4] = {vv.x, vv.y, vv.z, vv.w};
            #pragma unroll
            for (int i = 0; i < 4; i++) {
                float p = KP[(ty * 4 + i) * PAD + k];   // warp-broadcast
                #pragma unroll
                for (int j = 0; j < 4; j++)
                    o[i][j] = fmaf(p, vf[j], o[i][j]);
            }
        }
    }

    // ---- epilogue: normalize, write out[b][s][h*64+d] ----
    #pragma unroll
    for (int i = 0; i < 4; i++) {
        float inv = 1.f / l[i];
        int srow = w * 64 + ty * 4 + i;
        float4 r;
        r.x = o[i][0] * inv; r.y = o[i][1] * inv;
        r.z = o[i][2] * inv; r.w = o[i][3] * inv;
        *reinterpret_cast<float4*>(
            &out[(size_t)(b * SS + srow) * DD + h * HD + tx * 4]) = r;
    }
}

// ---------------------------------------------------------------------------
// Launch
// ---------------------------------------------------------------------------
extern "C" void kernel_launch(void* const* d_in, const int* in_sizes, int n_in,
                              void* d_out, int out_size) {
    const float* x   = (const float*)d_in[0];
    const float* kpm = (const float*)d_in[1];
    const float* Wq  = (const float*)d_in[2];
    const float* bq  = (const float*)d_in[3];
    const float* Wk  = (const float*)d_in[4];
    const float* bk  = (const float*)d_in[5];
    const float* Wv  = (const float*)d_in[6];
    const float* bv  = (const float*)d_in[7];
    float* out = (float*)d_out;

    dim3 ggrid(32, 8);
    qkv_gemm_kernel<<<ggrid, 256>>>(x, Wq, bq, 0);
    qkv_gemm_kernel<<<ggrid, 256>>>(x, Wk, bk, 1);
    qkv_gemm_kernel<<<ggrid, 256>>>(x, Wv, bv, 2);

    static int smem_set = 0;
    const int smem_bytes = SM_FLOATS * sizeof(float);   // 52480
    if (!smem_set) {
        cudaFuncSetAttribute(sparse_attn_kernel,
                             cudaFuncAttributeMaxDynamicSharedMemorySize,
                             smem_bytes);
        smem_set = 1;
    }
    dim3 agrid(32, HH, BB);
    sparse_attn_kernel<<<agrid, 256, smem_bytes>>>(kpm, out);
}

// round 5
// speedup vs baseline: 2.9656x; 1.7612x over previous
#include <cuda_runtime.h>
#include <math.h>
#include <stdint.h>

#define BB 2
#define SS 2048
#define DD 1024
#define HH 16
#define HD 64

// Scratch: q,k,v in [b][h][s][d] layout for attention-friendly access.
__device__ float g_q[BB*HH*SS*HD];
__device__ float g_k[BB*HH*SS*HD];
__device__ float g_v[BB*HH*SS*HD];

// ---------------------------------------------------------------------------
// tf32 helpers
// ---------------------------------------------------------------------------
__device__ __forceinline__ uint32_t f2tf32(float f) {
    uint32_t r;
    asm("cvt.rna.tf32.f32 %0, %1;" : "=r"(r) : "f"(f));
    return r;
}

__device__ __forceinline__ void mma_tf32(float c[4], const uint32_t a[4],
                                         const uint32_t b[2]) {
    asm volatile(
        "mma.sync.aligned.m16n8k8.row.col.f32.tf32.tf32.f32 "
        "{%0,%1,%2,%3}, {%4,%5,%6,%7}, {%8,%9}, {%0,%1,%2,%3};\n"
        : "+f"(c[0]), "+f"(c[1]), "+f"(c[2]), "+f"(c[3])
        : "r"(a[0]), "r"(a[1]), "r"(a[2]), "r"(a[3]),
          "r"(b[0]), "r"(b[1]));
}

// ---------------------------------------------------------------------------
// Fused QKV projection with tf32 tensor cores.
// Grid: (32 m-tiles, 8 n-tiles, 3 {q,k,v}); 256 threads = 8 warps.
// CTA tile 128x128, K-slice 16 (2 mma k-steps). Warp tile 64x32:
// warps laid out 2(m) x 4(n); per warp 4x4 mma tiles of m16n8k8.
// Smem row stride 136 words => fragment LDS hits all 32 banks (conflict-free).
// out[b][h][s][d] = sum_k x[b*S+s][k] * W[k][h*64+d] + bias[h*64+d]
// ---------------------------------------------------------------------------
#define LDW 136

__global__ void __launch_bounds__(256, 2)
qkv_gemm_tf32(const float* __restrict__ x,
              const float* __restrict__ Wq, const float* __restrict__ bq,
              const float* __restrict__ Wk, const float* __restrict__ bk,
              const float* __restrict__ Wv, const float* __restrict__ bv) {
    const int which = blockIdx.z;
    const float* W    = (which == 0) ? Wq : (which == 1) ? Wk : Wv;
    const float* bias = (which == 0) ? bq : (which == 1) ? bk : bv;
    float* out        = (which == 0) ? g_q : (which == 1) ? g_k : g_v;

    __shared__ uint32_t As[16][LDW];   // A transposed: As[k][m]
    __shared__ uint32_t Bs[16][LDW];   // B natural:    Bs[k][n]

    const int tid  = threadIdx.x;
    const int lane = tid & 31;
    const int warp = tid >> 5;
    const int wm = (warp & 1) * 64;    // warp m offset
    const int wn = (warp >> 1) * 32;   // warp n offset
    const int row0 = blockIdx.x * 128;
    const int col0 = blockIdx.y * 128;

    const int tig = lane & 3;          // thread-in-group (k index)
    const int grp = lane >> 2;         // group (row/col index)

    float c[4][4][4];
    #pragma unroll
    for (int mt = 0; mt < 4; mt++)
        #pragma unroll
        for (int nt = 0; nt < 4; nt++)
            #pragma unroll
            for (int r = 0; r < 4; r++) c[mt][nt][r] = 0.f;

    for (int k0 = 0; k0 < DD; k0 += 16) {
        // ---- stage A (128x16, transposed) and B (16x128) as tf32 ----
        #pragma unroll
        for (int i = 0; i < 2; i++) {
            int idx = tid + i * 256;
            // A: 4 lanes per row, 64B per row chunk (coalesced)
            int ar = idx >> 2, akq = (idx & 3) * 4;
            float4 xv = *reinterpret_cast<const float4*>(
                &x[(size_t)(row0 + ar) * DD + k0 + akq]);
            As[akq + 0][ar] = f2tf32(xv.x);
            As[akq + 1][ar] = f2tf32(xv.y);
            As[akq + 2][ar] = f2tf32(xv.z);
            As[akq + 3][ar] = f2tf32(xv.w);
            // B: full 128-float rows (coalesced)
            int bkk = idx >> 5, bcc = (idx & 31) * 4;
            float4 wv = *reinterpret_cast<const float4*>(
                &W[(size_t)(k0 + bkk) * DD + col0 + bcc]);
            uint4 wt;
            wt.x = f2tf32(wv.x); wt.y = f2tf32(wv.y);
            wt.z = f2tf32(wv.z); wt.w = f2tf32(wv.w);
            *reinterpret_cast<uint4*>(&Bs[bkk][bcc]) = wt;
        }
        __syncthreads();

        // ---- 2 mma k-steps of 8 ----
        #pragma unroll
        for (int ks = 0; ks < 16; ks += 8) {
            const int ak = ks + tig;
            uint32_t a[4][4], b[4][2];
            #pragma unroll
            for (int mt = 0; mt < 4; mt++) {
                int r = wm + mt * 16 + grp;
                a[mt][0] = As[ak][r];
                a[mt][1] = As[ak][r + 8];
                a[mt][2] = As[ak + 4][r];
                a[mt][3] = As[ak + 4][r + 8];
            }
            #pragma unroll
            for (int nt = 0; nt < 4; nt++) {
                int n = wn + nt * 8 + grp;
                b[nt][0] = Bs[ak][n];
                b[nt][1] = Bs[ak + 4][n];
            }
            #pragma unroll
            for (int mt = 0; mt < 4; mt++)
                #pragma unroll
                for (int nt = 0; nt < 4; nt++)
                    mma_tf32(c[mt][nt], a[mt], b[nt]);
        }
        __syncthreads();
    }

    // ---- epilogue: +bias, scatter to [b][h][s][d] (float2 stores) ----
    #pragma unroll
    for (int nt = 0; nt < 4; nt++) {
        const int col = col0 + wn + nt * 8 + tig * 2;
        const int h_ = col >> 6;
        const int d_ = col & 63;
        const float2 bb = *reinterpret_cast<const float2*>(&bias[col]);
        #pragma unroll
        for (int mt = 0; mt < 4; mt++) {
            int rowa = row0 + wm + mt * 16 + grp;
            #pragma unroll
            for (int half = 0; half < 2; half++) {
                int row = rowa + half * 8;
                int b_ = row >> 11;
                int s_ = row & 2047;
                float2 rv;
                rv.x = c[mt][nt][half * 2 + 0] + bb.x;
                rv.y = c[mt][nt][half * 2 + 1] + bb.y;
                *reinterpret_cast<float2*>(
                    &out[((size_t)((b_ * HH + h_) * SS) + s_) * HD + d_]) = rv;
            }
        }
    }
}

// ---------------------------------------------------------------------------
// Flash-style block-sparse attention over 64-query windows (unchanged R3).
// Grid: (window 0..31, head, batch). 256 threads = (ty 0..15) x (tx 0..15).
// ---------------------------------------------------------------------------
#define PAD 68
#define SM_Q 0
#define SM_KP (64*PAD)
#define SM_V  (2*64*PAD)
#define SM_KPM (3*64*PAD)
#define SM_FLOATS (3*64*PAD + 64)

__global__ void __launch_bounds__(256)
sparse_attn_kernel(const float* __restrict__ kpm, float* __restrict__ out) {
    extern __shared__ float sm[];
    float* Qst  = sm + SM_Q;
    float* KP   = sm + SM_KP;
    float* Vs   = sm + SM_V;
    float* kpms = sm + SM_KPM;

    const int w = blockIdx.x;
    const int h = blockIdx.y;
    const int b = blockIdx.z;

    const int tid = threadIdx.x;
    const int tx  = tid & 15;
    const int ty  = tid >> 4;

    const size_t head_base = (size_t)(b * HH + h) * SS * HD;

    {
        const int r  = tid >> 2;
        const int dq = (tid & 3) << 4;
        const float* qrow = g_q + head_base + (size_t)(w * 64 + r) * HD;
        #pragma unroll
        for (int u = 0; u < 4; u++) {
            float4 qv = *reinterpret_cast<const float4*>(&qrow[dq + u * 4]);
            Qst[(dq + u * 4 + 0) * PAD + r] = qv.x;
            Qst[(dq + u * 4 + 1) * PAD + r] = qv.y;
            Qst[(dq + u * 4 + 2) * PAD + r] = qv.z;
            Qst[(dq + u * 4 + 3) * PAD + r] = qv.w;
        }
    }

    float m[4], l[4], o[4][4];
    #pragma unroll
    for (int i = 0; i < 4; i++) {
        m[i] = -1e30f; l[i] = 0.f;
        #pragma unroll
        for (int j = 0; j < 4; j++) o[i][j] = 0.f;
    }

    const float scale = 0.125f;
    const int nkt = (w + 3) >> 2;
    const bool winMasked = (tx >> 2) > (ty >> 2);

    for (int it = 0; it <= nkt; it++) {
        const bool isWin = (it == nkt);

        __syncthreads();

        {
            const int r  = tid >> 2;
            const int dq = (tid & 3) << 4;
            int kb; bool valid;
            if (isWin) { kb = 4 * w + (r >> 4); valid = true; }
            else {
                int g = it * 4 + (r >> 4);
                valid = (g < w);
                kb = 4 * g + 3;
            }
            const float* krow = g_k + head_base + (size_t)(kb * 16 + (r & 15)) * HD;
            const float* vrow = g_v + head_base + (size_t)(kb * 16 + (r & 15)) * HD;
            const float4 z4 = make_float4(0.f, 0.f, 0.f, 0.f);
            #pragma unroll
            for (int u = 0; u < 4; u++) {
                float4 kv = valid ? *reinterpret_cast<const float4*>(&krow[dq + u * 4]) : z4;
                KP[(dq + u * 4 + 0) * PAD + r] = kv.x;
                KP[(dq + u * 4 + 1) * PAD + r] = kv.y;
                KP[(dq + u * 4 + 2) * PAD + r] = kv.z;
                KP[(dq + u * 4 + 3) * PAD + r] = kv.w;
                float4 vv = valid ? *reinterpret_cast<const float4*>(&vrow[dq + u * 4]) : z4;
                *reinterpret_cast<float4*>(&Vs[r * PAD + dq + u * 4]) = vv;
            }
            if (tid < 64) {
                int kk = tid;
                int kb2; bool v2;
                if (isWin) { kb2 = 4 * w + (kk >> 4); v2 = true; }
                else {
                    int g2 = it * 4 + (kk >> 4);
                    v2 = (g2 < w);
                    kb2 = 4 * g2 + 3;
                }
                kpms[kk] = v2 ? kpm[b * SS + kb2 * 16 + (kk & 15)] : -INFINITY;
            }
        }
        __syncthreads();

        float s[4][4] = {};
        #pragma unroll 8
        for (int d = 0; d < 64; d++) {
            float4 a = *reinterpret_cast<const float4*>(&Qst[d * PAD + ty * 4]);
            float4 bf = *reinterpret_cast<const float4*>(&KP[d * PAD + tx * 4]);
            float av[4] = {a.x, a.y, a.z, a.w};
            float bv[4] = {bf.x, bf.y, bf.z, bf.w};
            #pragma unroll
            for (int i = 0; i < 4; i++)
                #pragma unroll
                for (int j = 0; j < 4; j++)
                    s[i][j] = fmaf(av[i], bv[j], s[i][j]);
        }

        #pragma unroll
        for (int i = 0; i < 4; i++)
            #pragma unroll
            for (int j = 0; j < 4; j++) {
                float val = s[i][j] * scale + kpms[tx * 4 + j];
                if (isWin && winMasked) val = -INFINITY;
                s[i][j] = val;
            }

        float rm[4], rs[4], alpha[4];
        #pragma unroll
        for (int i = 0; i < 4; i++) {
            rm[i] = fmaxf(fmaxf(s[i][0], s[i][1]), fmaxf(s[i][2], s[i][3]));
            #pragma unroll
            for (int off = 1; off < 16; off <<= 1)
                rm[i] = fmaxf(rm[i], __shfl_xor_sync(0xffffffffu, rm[i], off));
        }
        #pragma unroll
        for (int i = 0; i < 4; i++) {
            float newm = fmaxf(m[i], rm[i]);
            alpha[i] = __expf(m[i] - newm);
            m[i] = newm;
            float acc = 0.f;
            #pragma unroll
            for (int j = 0; j < 4; j++) {
                float p = __expf(s[i][j] - newm);
                s[i][j] = p;
                acc += p;
            }
            rs[i] = acc;
            #pragma unroll
            for (int off = 1; off < 16; off <<= 1)
                rs[i] += __shfl_xor_sync(0xffffffffu, rs[i], off);
            l[i] = l[i] * alpha[i] + rs[i];
            #pragma unroll
            for (int j = 0; j < 4; j++) o[i][j] *= alpha[i];
        }

        __syncthreads();

        #pragma unroll
        for (int i = 0; i < 4; i++)
            *reinterpret_cast<float4*>(&KP[(ty * 4 + i) * PAD + tx * 4]) =
                make_float4(s[i][0], s[i][1], s[i][2], s[i][3]);
        __syncthreads();

        #pragma unroll 8
        for (int k = 0; k < 64; k++) {
            float4 vv = *reinterpret_cast<const float4*>(&Vs[k * PAD + tx * 4]);
            float vf[4] = {vv.x, vv.y, vv.z, vv.w};
            #pragma unroll
            for (int i = 0; i < 4; i++) {
                float p = KP[(ty * 4 + i) * PAD + k];
                #pragma unroll
                for (int j = 0; j < 4; j++)
                    o[i][j] = fmaf(p, vf[j], o[i][j]);
            }
        }
    }

    #pragma unroll
    for (int i = 0; i < 4; i++) {
        float inv = 1.f / l[i];
        int srow = w * 64 + ty * 4 + i;
        float4 r;
        r.x = o[i][0] * inv; r.y = o[i][1] * inv;
        r.z = o[i][2] * inv; r.w = o[i][3] * inv;
        *reinterpret_cast<float4*>(
            &out[(size_t)(b * SS + srow) * DD + h * HD + tx * 4]) = r;
    }
}

// ---------------------------------------------------------------------------
// Launch
// ---------------------------------------------------------------------------
extern "C" void kernel_launch(void* const* d_in, const int* in_sizes, int n_in,
                              void* d_out, int out_size) {
    const float* x   = (const float*)d_in[0];
    const float* kpm = (const float*)d_in[1];
    const float* Wq  = (const float*)d_in[2];
    const float* bq  = (const float*)d_in[3];
    const float* Wk  = (const float*)d_in[4];
    const float* bk  = (const float*)d_in[5];
    const float* Wv  = (const float*)d_in[6];
    const float* bv  = (const float*)d_in[7];
    float* out = (float*)d_out;

    dim3 ggrid(32, 8, 3);
    qkv_gemm_tf32<<<ggrid, 256>>>(x, Wq, bq, Wk, bk, Wv, bv);

    static int smem_set = 0;
    const int smem_bytes = SM_FLOATS * sizeof(float);   // 52480
    if (!smem_set) {
        cudaFuncSetAttribute(sparse_attn_kernel,
                             cudaFuncAttributeMaxDynamicSharedMemorySize,
                             smem_bytes);
        smem_set = 1;
    }
    dim3 agrid(32, HH, BB);
    sparse_attn_kernel<<<agrid, 256, smem_bytes>>>(kpm, out);
}

// round 6
// speedup vs baseline: 3.7176x; 1.2536x over previous
#include <cuda_runtime.h>
#include <math.h>
#include <stdint.h>

#define BB 2
#define SS 2048
#define DD 1024
#define HH 16
#define HD 64

// Scratch: q,k,v in [b][h][s][d] layout for attention-friendly access.
__device__ float g_q[BB*HH*SS*HD];
__device__ float g_k[BB*HH*SS*HD];
__device__ float g_v[BB*HH*SS*HD];

// ---------------------------------------------------------------------------
// tf32 helpers
// ---------------------------------------------------------------------------
__device__ __forceinline__ uint32_t f2tf32(float f) {
    uint32_t r;
    asm("cvt.rna.tf32.f32 %0, %1;" : "=r"(r) : "f"(f));
    return r;
}

__device__ __forceinline__ void mma_tf32(float c[4], const uint32_t a[4],
                                         const uint32_t b[2]) {
    asm volatile(
        "mma.sync.aligned.m16n8k8.row.col.f32.tf32.tf32.f32 "
        "{%0,%1,%2,%3}, {%4,%5,%6,%7}, {%8,%9}, {%0,%1,%2,%3};\n"
        : "+f"(c[0]), "+f"(c[1]), "+f"(c[2]), "+f"(c[3])
        : "r"(a[0]), "r"(a[1]), "r"(a[2]), "r"(a[3]),
          "r"(b[0]), "r"(b[1]));
}

// ---------------------------------------------------------------------------
// Fused QKV projection with tf32 tensor cores (unchanged from R4).
// ---------------------------------------------------------------------------
#define LDW 136

__global__ void __launch_bounds__(256, 2)
qkv_gemm_tf32(const float* __restrict__ x,
              const float* __restrict__ Wq, const float* __restrict__ bq,
              const float* __restrict__ Wk, const float* __restrict__ bk,
              const float* __restrict__ Wv, const float* __restrict__ bv) {
    const int which = blockIdx.z;
    const float* W    = (which == 0) ? Wq : (which == 1) ? Wk : Wv;
    const float* bias = (which == 0) ? bq : (which == 1) ? bk : bv;
    float* out        = (which == 0) ? g_q : (which == 1) ? g_k : g_v;

    __shared__ uint32_t As[16][LDW];
    __shared__ uint32_t Bs[16][LDW];

    const int tid  = threadIdx.x;
    const int lane = tid & 31;
    const int warp = tid >> 5;
    const int wm = (warp & 1) * 64;
    const int wn = (warp >> 1) * 32;
    const int row0 = blockIdx.x * 128;
    const int col0 = blockIdx.y * 128;

    const int tig = lane & 3;
    const int grp = lane >> 2;

    float c[4][4][4];
    #pragma unroll
    for (int mt = 0; mt < 4; mt++)
        #pragma unroll
        for (int nt = 0; nt < 4; nt++)
            #pragma unroll
            for (int r = 0; r < 4; r++) c[mt][nt][r] = 0.f;

    for (int k0 = 0; k0 < DD; k0 += 16) {
        #pragma unroll
        for (int i = 0; i < 2; i++) {
            int idx = tid + i * 256;
            int ar = idx >> 2, akq = (idx & 3) * 4;
            float4 xv = *reinterpret_cast<const float4*>(
                &x[(size_t)(row0 + ar) * DD + k0 + akq]);
            As[akq + 0][ar] = f2tf32(xv.x);
            As[akq + 1][ar] = f2tf32(xv.y);
            As[akq + 2][ar] = f2tf32(xv.z);
            As[akq + 3][ar] = f2tf32(xv.w);
            int bkk = idx >> 5, bcc = (idx & 31) * 4;
            float4 wv = *reinterpret_cast<const float4*>(
                &W[(size_t)(k0 + bkk) * DD + col0 + bcc]);
            uint4 wt;
            wt.x = f2tf32(wv.x); wt.y = f2tf32(wv.y);
            wt.z = f2tf32(wv.z); wt.w = f2tf32(wv.w);
            *reinterpret_cast<uint4*>(&Bs[bkk][bcc]) = wt;
        }
        __syncthreads();

        #pragma unroll
        for (int ks = 0; ks < 16; ks += 8) {
            const int ak = ks + tig;
            uint32_t a[4][4], b[4][2];
            #pragma unroll
            for (int mt = 0; mt < 4; mt++) {
                int r = wm + mt * 16 + grp;
                a[mt][0] = As[ak][r];
                a[mt][1] = As[ak][r + 8];
                a[mt][2] = As[ak + 4][r];
                a[mt][3] = As[ak + 4][r + 8];
            }
            #pragma unroll
            for (int nt = 0; nt < 4; nt++) {
                int n = wn + nt * 8 + grp;
                b[nt][0] = Bs[ak][n];
                b[nt][1] = Bs[ak + 4][n];
            }
            #pragma unroll
            for (int mt = 0; mt < 4; mt++)
                #pragma unroll
                for (int nt = 0; nt < 4; nt++)
                    mma_tf32(c[mt][nt], a[mt], b[nt]);
        }
        __syncthreads();
    }

    #pragma unroll
    for (int nt = 0; nt < 4; nt++) {
        const int col = col0 + wn + nt * 8 + tig * 2;
        const int h_ = col >> 6;
        const int d_ = col & 63;
        const float2 bb = *reinterpret_cast<const float2*>(&bias[col]);
        #pragma unroll
        for (int mt = 0; mt < 4; mt++) {
            int rowa = row0 + wm + mt * 16 + grp;
            #pragma unroll
            for (int half = 0; half < 2; half++) {
                int row = rowa + half * 8;
                int b_ = row >> 11;
                int s_ = row & 2047;
                float2 rv;
                rv.x = c[mt][nt][half * 2 + 0] + bb.x;
                rv.y = c[mt][nt][half * 2 + 1] + bb.y;
                *reinterpret_cast<float2*>(
                    &out[((size_t)((b_ * HH + h_) * SS) + s_) * HD + d_]) = rv;
            }
        }
    }
}

// ---------------------------------------------------------------------------
// tf32-mma flash block-sparse attention over 64-query windows.
// Grid: (window 0..31, head, batch). 128 threads = 4 warps.
// Warp w owns query rows wq=16w..16w+15 (one m16 tile) x all 64 keys (8 n8).
// S = Q K^T : A = Q[q][d] row-major, B = K[key][d] (native layout IS col-major
//             k x n with k=d) -> no transpose staging.
// P V      : A = P[q][key] row-major (smem, tf32), B = Vt[d][key] (staged
//             transposed; col-major k x n with k=key, n=d).
// Softmax rows live entirely in one warp -> quad shfl reductions only.
// Smem: Qs[64][68] (staged once), KP[64][68] (K, then reused for P),
//       Vt[64][68], kpms[64]  => 52.5 KB.
// ---------------------------------------------------------------------------
#define PAD 68
#define SM_Q 0
#define SM_KP (64*PAD)
#define SM_VT (2*64*PAD)
#define SM_KPM (3*64*PAD)
#define SM_FLOATS (3*64*PAD + 64)

__global__ void __launch_bounds__(128)
sparse_attn_kernel(const float* __restrict__ kpm, float* __restrict__ out) {
    extern __shared__ float smf[];
    uint32_t* Qs  = reinterpret_cast<uint32_t*>(smf + SM_Q);
    uint32_t* KP  = reinterpret_cast<uint32_t*>(smf + SM_KP);
    uint32_t* Vt  = reinterpret_cast<uint32_t*>(smf + SM_VT);
    float*    kpms = smf + SM_KPM;

    const int w = blockIdx.x;
    const int h = blockIdx.y;
    const int b = blockIdx.z;

    const int tid  = threadIdx.x;
    const int lane = tid & 31;
    const int warp = tid >> 5;       // 0..3
    const int wq   = warp * 16;      // query row base for this warp
    const int grp  = lane >> 2;      // 0..7
    const int tig  = lane & 3;       // 0..3

    const size_t head_base = (size_t)(b * HH + h) * SS * HD;

    // ---- Stage Q (64 x 64) natural as tf32: Qs[q][d] ----
    {
        const int r  = tid >> 1;             // row 0..63
        const int dh = (tid & 1) * 32;       // d half
        const float* qrow = g_q + head_base + (size_t)(w * 64 + r) * HD + dh;
        #pragma unroll
        for (int u = 0; u < 8; u++) {
            float4 qv = *reinterpret_cast<const float4*>(&qrow[u * 4]);
            uint4 qt;
            qt.x = f2tf32(qv.x); qt.y = f2tf32(qv.y);
            qt.z = f2tf32(qv.z); qt.w = f2tf32(qv.w);
            *reinterpret_cast<uint4*>(&Qs[r * PAD + dh + u * 4]) = qt;
        }
    }

    // Persistent state: O accum (16 q x 64 d warp tile), row stats.
    float o[8][4];
    #pragma unroll
    for (int nt = 0; nt < 8; nt++)
        #pragma unroll
        for (int r = 0; r < 4; r++) o[nt][r] = 0.f;
    float m0 = -1e30f, m1 = -1e30f, l0 = 0.f, l1 = 0.f;

    const float scale = 0.125f;
    const int nkt = (w + 3) >> 2;
    const int row_a = wq + grp;        // rows this thread owns
    const int row_b = wq + grp + 8;

    for (int it = 0; it <= nkt; it++) {
        const bool isWin = (it == nkt);

        __syncthreads();   // prior-tile P/Vt consumers done

        // ---- Stage K natural (KP[key][d]) + V transposed (Vt[d][key]) ----
        {
            const int r  = tid >> 1;
            const int dh = (tid & 1) * 32;
            int kb; bool valid;
            if (isWin) { kb = 4 * w + (r >> 4); valid = true; }
            else {
                int g = it * 4 + (r >> 4);
                valid = (g < w);
                kb = 4 * g + 3;
            }
            const float* krow = g_k + head_base + (size_t)(kb * 16 + (r & 15)) * HD + dh;
            const float* vrow = g_v + head_base + (size_t)(kb * 16 + (r & 15)) * HD + dh;
            const float4 z4 = make_float4(0.f, 0.f, 0.f, 0.f);
            #pragma unroll
            for (int u = 0; u < 8; u++) {
                float4 kv = valid ? *reinterpret_cast<const float4*>(&krow[u * 4]) : z4;
                uint4 kt;
                kt.x = f2tf32(kv.x); kt.y = f2tf32(kv.y);
                kt.z = f2tf32(kv.z); kt.w = f2tf32(kv.w);
                *reinterpret_cast<uint4*>(&KP[r * PAD + dh + u * 4]) = kt;
                float4 vv = valid ? *reinterpret_cast<const float4*>(&vrow[u * 4]) : z4;
                Vt[(dh + u * 4 + 0) * PAD + r] = f2tf32(vv.x);
                Vt[(dh + u * 4 + 1) * PAD + r] = f2tf32(vv.y);
                Vt[(dh + u * 4 + 2) * PAD + r] = f2tf32(vv.z);
                Vt[(dh + u * 4 + 3) * PAD + r] = f2tf32(vv.w);
            }
            if (tid < 64) {
                int kk = tid;
                int kb2; bool v2;
                if (isWin) { kb2 = 4 * w + (kk >> 4); v2 = true; }
                else {
                    int g2 = it * 4 + (kk >> 4);
                    v2 = (g2 < w);
                    kb2 = 4 * g2 + 3;
                }
                kpms[kk] = v2 ? kpm[b * SS + kb2 * 16 + (kk & 15)] : -INFINITY;
            }
        }
        __syncthreads();

        // ---- S = Q K^T : warp tile 16 x 64 (8 n-tiles) ----
        float sc[8][4];
        #pragma unroll
        for (int nt = 0; nt < 8; nt++)
            #pragma unroll
            for (int r = 0; r < 4; r++) sc[nt][r] = 0.f;

        #pragma unroll
        for (int ks = 0; ks < 64; ks += 8) {
            uint32_t a[4];
            a[0] = Qs[row_a * PAD + ks + tig];
            a[1] = Qs[row_b * PAD + ks + tig];
            a[2] = Qs[row_a * PAD + ks + tig + 4];
            a[3] = Qs[row_b * PAD + ks + tig + 4];
            #pragma unroll
            for (int nt = 0; nt < 8; nt++) {
                uint32_t bfr[2];
                bfr[0] = KP[(nt * 8 + grp) * PAD + ks + tig];
                bfr[1] = KP[(nt * 8 + grp) * PAD + ks + tig + 4];
                mma_tf32(sc[nt], a, bfr);
            }
        }

        // ---- scale + kpm + window mask (accumulator layout) ----
        #pragma unroll
        for (int nt = 0; nt < 8; nt++) {
            #pragma unroll
            for (int cc = 0; cc < 2; cc++) {
                int col = nt * 8 + tig * 2 + cc;
                float kv = kpms[col];
                float v0 = sc[nt][cc]     * scale + kv;   // row_a
                float v1 = sc[nt][2 + cc] * scale + kv;   // row_b
                if (isWin) {
                    if ((col >> 4) > (row_a >> 4)) v0 = -INFINITY;
                    if ((col >> 4) > (row_b >> 4)) v1 = -INFINITY;
                }
                sc[nt][cc] = v0;
                sc[nt][2 + cc] = v1;
            }
        }

        // ---- online softmax: rows row_a (regs 0,1), row_b (regs 2,3) ----
        float mx0 = -INFINITY, mx1 = -INFINITY;
        #pragma unroll
        for (int nt = 0; nt < 8; nt++) {
            mx0 = fmaxf(mx0, fmaxf(sc[nt][0], sc[nt][1]));
            mx1 = fmaxf(mx1, fmaxf(sc[nt][2], sc[nt][3]));
        }
        mx0 = fmaxf(mx0, __shfl_xor_sync(0xffffffffu, mx0, 1));
        mx0 = fmaxf(mx0, __shfl_xor_sync(0xffffffffu, mx0, 2));
        mx1 = fmaxf(mx1, __shfl_xor_sync(0xffffffffu, mx1, 1));
        mx1 = fmaxf(mx1, __shfl_xor_sync(0xffffffffu, mx1, 2));

        const float nm0 = fmaxf(m0, mx0);
        const float nm1 = fmaxf(m1, mx1);
        const float al0 = __expf(m0 - nm0);
        const float al1 = __expf(m1 - nm1);
        m0 = nm0; m1 = nm1;

        float rs0 = 0.f, rs1 = 0.f;
        #pragma unroll
        for (int nt = 0; nt < 8; nt++) {
            #pragma unroll
            for (int cc = 0; cc < 2; cc++) {
                float p0 = __expf(sc[nt][cc] - nm0);
                float p1 = __expf(sc[nt][2 + cc] - nm1);
                sc[nt][cc] = p0;
                sc[nt][2 + cc] = p1;
                rs0 += p0; rs1 += p1;
            }
        }
        rs0 += __shfl_xor_sync(0xffffffffu, rs0, 1);
        rs0 += __shfl_xor_sync(0xffffffffu, rs0, 2);
        rs1 += __shfl_xor_sync(0xffffffffu, rs1, 1);
        rs1 += __shfl_xor_sync(0xffffffffu, rs1, 2);
        l0 = l0 * al0 + rs0;
        l1 = l1 * al1 + rs1;
        #pragma unroll
        for (int nt = 0; nt < 8; nt++) {
            o[nt][0] *= al0; o[nt][1] *= al0;
            o[nt][2] *= al1; o[nt][3] *= al1;
        }

        __syncthreads();   // all warps done reading K before P overwrite

        // ---- write P (tf32) into KP as [q][key] ----
        #pragma unroll
        for (int nt = 0; nt < 8; nt++) {
            uint2 p0, p1;
            p0.x = f2tf32(sc[nt][0]); p0.y = f2tf32(sc[nt][1]);
            p1.x = f2tf32(sc[nt][2]); p1.y = f2tf32(sc[nt][3]);
            *reinterpret_cast<uint2*>(&KP[row_a * PAD + nt * 8 + tig * 2]) = p0;
            *reinterpret_cast<uint2*>(&KP[row_b * PAD + nt * 8 + tig * 2]) = p1;
        }
        __syncwarp();   // P rows/cols for this warp's PV are warp-local

        // ---- O += P V ----
        #pragma unroll
        for (int ks = 0; ks < 64; ks += 8) {
            uint32_t a[4];
            a[0] = KP[row_a * PAD + ks + tig];
            a[1] = KP[row_b * PAD + ks + tig];
            a[2] = KP[row_a * PAD + ks + tig + 4];
            a[3] = KP[row_b * PAD + ks + tig + 4];
            #pragma unroll
            for (int nt = 0; nt < 8; nt++) {
                uint32_t bfr[2];
                bfr[0] = Vt[(nt * 8 + grp) * PAD + ks + tig];
                bfr[1] = Vt[(nt * 8 + grp) * PAD + ks + tig + 4];
                mma_tf32(o[nt], a, bfr);
            }
        }
    }

    // ---- epilogue: normalize, write out[b][s][h*64+d] ----
    const float inv0 = 1.f / l0;
    const float inv1 = 1.f / l1;
    #pragma unroll
    for (int nt = 0; nt < 8; nt++) {
        int d_ = nt * 8 + tig * 2;
        float2 r0, r1;
        r0.x = o[nt][0] * inv0; r0.y = o[nt][1] * inv0;
        r1.x = o[nt][2] * inv1; r1.y = o[nt][3] * inv1;
        *reinterpret_cast<float2*>(
            &out[(size_t)(b * SS + w * 64 + row_a) * DD + h * HD + d_]) = r0;
        *reinterpret_cast<float2*>(
            &out[(size_t)(b * SS + w * 64 + row_b) * DD + h * HD + d_]) = r1;
    }
}

// ---------------------------------------------------------------------------
// Launch
// ---------------------------------------------------------------------------
extern "C" void kernel_launch(void* const* d_in, const int* in_sizes, int n_in,
                              void* d_out, int out_size) {
    const float* x   = (const float*)d_in[0];
    const float* kpm = (const float*)d_in[1];
    const float* Wq  = (const float*)d_in[2];
    const float* bq  = (const float*)d_in[3];
    const float* Wk  = (const float*)d_in[4];
    const float* bk  = (const float*)d_in[5];
    const float* Wv  = (const float*)d_in[6];
    const float* bv  = (const float*)d_in[7];
    float* out = (float*)d_out;

    dim3 ggrid(32, 8, 3);
    qkv_gemm_tf32<<<ggrid, 256>>>(x, Wq, bq, Wk, bk, Wv, bv);

    static int smem_set = 0;
    const int smem_bytes = SM_FLOATS * sizeof(float);   // 52480
    if (!smem_set) {
        cudaFuncSetAttribute(sparse_attn_kernel,
                             cudaFuncAttributeMaxDynamicSharedMemorySize,
                             smem_bytes);
        smem_set = 1;
    }
    dim3 agrid(32, HH, BB);
    sparse_attn_kernel<<<agrid, 128, smem_bytes>>>(kpm, out);
}

// round 7
// speedup vs baseline: 4.1339x; 1.1120x over previous
#include <cuda_runtime.h>
#include <math.h>
#include <stdint.h>

#define BB 2
#define SS 2048
#define DD 1024
#define HH 16
#define HD 64

// Scratch: q,k,v in [b][h][s][d] layout for attention-friendly access.
__device__ float g_q[BB*HH*SS*HD];
__device__ float g_k[BB*HH*SS*HD];
__device__ float g_v[BB*HH*SS*HD];

// ---------------------------------------------------------------------------
// tf32 helpers
// ---------------------------------------------------------------------------
__device__ __forceinline__ uint32_t f2tf32(float f) {
    uint32_t r;
    asm("cvt.rna.tf32.f32 %0, %1;" : "=r"(r) : "f"(f));
    return r;
}

__device__ __forceinline__ void mma_tf32(float c[4], const uint32_t a[4],
                                         const uint32_t b[2]) {
    asm volatile(
        "mma.sync.aligned.m16n8k8.row.col.f32.tf32.tf32.f32 "
        "{%0,%1,%2,%3}, {%4,%5,%6,%7}, {%8,%9}, {%0,%1,%2,%3};\n"
        : "+f"(c[0]), "+f"(c[1]), "+f"(c[2]), "+f"(c[3])
        : "r"(a[0]), "r"(a[1]), "r"(a[2]), "r"(a[3]),
          "r"(b[0]), "r"(b[1]));
}

// ---------------------------------------------------------------------------
// Fused QKV projection, tf32 tensor cores, double-buffered smem pipeline.
// Grid: (32 m-tiles, 8 n-tiles, 3 {q,k,v}); 256 threads = 8 warps.
// CTA tile 128x128, K-slice 16. Per iteration: prefetch next slice to regs,
// mma current buffer, store regs to alternate buffer, one syncthreads.
// ---------------------------------------------------------------------------
#define LDW 136

__global__ void __launch_bounds__(256, 2)
qkv_gemm_tf32(const float* __restrict__ x,
              const float* __restrict__ Wq, const float* __restrict__ bq,
              const float* __restrict__ Wk, const float* __restrict__ bk,
              const float* __restrict__ Wv, const float* __restrict__ bv) {
    const int which = blockIdx.z;
    const float* W    = (which == 0) ? Wq : (which == 1) ? Wk : Wv;
    const float* bias = (which == 0) ? bq : (which == 1) ? bk : bv;
    float* out        = (which == 0) ? g_q : (which == 1) ? g_k : g_v;

    __shared__ uint32_t As[2][16][LDW];
    __shared__ uint32_t Bs[2][16][LDW];

    const int tid  = threadIdx.x;
    const int lane = tid & 31;
    const int warp = tid >> 5;
    const int wm = (warp & 1) * 64;
    const int wn = (warp >> 1) * 32;
    const int row0 = blockIdx.x * 128;
    const int col0 = blockIdx.y * 128;

    const int tig = lane & 3;
    const int grp = lane >> 2;

    // load mappings (2 chunks per thread)
    const int ar0 = tid >> 1;                 // chunk i: ar = (tid + i*256)>>2
    // chunk addressing computed inline below.

    float c[4][4][4];
    #pragma unroll
    for (int mt = 0; mt < 4; mt++)
        #pragma unroll
        for (int nt = 0; nt < 4; nt++)
            #pragma unroll
            for (int r = 0; r < 4; r++) c[mt][nt][r] = 0.f;
    (void)ar0;

    float4 xa[2], wv[2];

    // ---- prologue: load and stage K-slice 0 into buffer 0 ----
    #pragma unroll
    for (int i = 0; i < 2; i++) {
        int idx = tid + i * 256;
        int ar = idx >> 2, akq = (idx & 3) * 4;
        xa[i] = *reinterpret_cast<const float4*>(&x[(size_t)(row0 + ar) * DD + akq]);
        int bkk = idx >> 5, bcc = (idx & 31) * 4;
        wv[i] = *reinterpret_cast<const float4*>(&W[(size_t)bkk * DD + col0 + bcc]);
    }
    #pragma unroll
    for (int i = 0; i < 2; i++) {
        int idx = tid + i * 256;
        int ar = idx >> 2, akq = (idx & 3) * 4;
        As[0][akq + 0][ar] = f2tf32(xa[i].x);
        As[0][akq + 1][ar] = f2tf32(xa[i].y);
        As[0][akq + 2][ar] = f2tf32(xa[i].z);
        As[0][akq + 3][ar] = f2tf32(xa[i].w);
        int bkk = idx >> 5, bcc = (idx & 31) * 4;
        uint4 wt;
        wt.x = f2tf32(wv[i].x); wt.y = f2tf32(wv[i].y);
        wt.z = f2tf32(wv[i].z); wt.w = f2tf32(wv[i].w);
        *reinterpret_cast<uint4*>(&Bs[0][bkk][bcc]) = wt;
    }
    __syncthreads();

    for (int kt = 0; kt < 64; kt++) {
        const int buf = kt & 1;

        // ---- prefetch next K-slice into registers (latency hidden by mma) ----
        if (kt < 63) {
            const int k0 = (kt + 1) * 16;
            #pragma unroll
            for (int i = 0; i < 2; i++) {
                int idx = tid + i * 256;
                int ar = idx >> 2, akq = (idx & 3) * 4;
                xa[i] = *reinterpret_cast<const float4*>(
                    &x[(size_t)(row0 + ar) * DD + k0 + akq]);
                int bkk = idx >> 5, bcc = (idx & 31) * 4;
                wv[i] = *reinterpret_cast<const float4*>(
                    &W[(size_t)(k0 + bkk) * DD + col0 + bcc]);
            }
        }

        // ---- mma on current buffer ----
        #pragma unroll
        for (int ks = 0; ks < 16; ks += 8) {
            const int ak = ks + tig;
            uint32_t a[4][4], b[4][2];
            #pragma unroll
            for (int mt = 0; mt < 4; mt++) {
                int r = wm + mt * 16 + grp;
                a[mt][0] = As[buf][ak][r];
                a[mt][1] = As[buf][ak][r + 8];
                a[mt][2] = As[buf][ak + 4][r];
                a[mt][3] = As[buf][ak + 4][r + 8];
            }
            #pragma unroll
            for (int nt = 0; nt < 4; nt++) {
                int n = wn + nt * 8 + grp;
                b[nt][0] = Bs[buf][ak][n];
                b[nt][1] = Bs[buf][ak + 4][n];
            }
            #pragma unroll
            for (int mt = 0; mt < 4; mt++)
                #pragma unroll
                for (int nt = 0; nt < 4; nt++)
                    mma_tf32(c[mt][nt], a[mt], b[nt]);
        }

        // ---- store prefetched slice to alternate buffer ----
        if (kt < 63) {
            const int nb = buf ^ 1;
            #pragma unroll
            for (int i = 0; i < 2; i++) {
                int idx = tid + i * 256;
                int ar = idx >> 2, akq = (idx & 3) * 4;
                As[nb][akq + 0][ar] = f2tf32(xa[i].x);
                As[nb][akq + 1][ar] = f2tf32(xa[i].y);
                As[nb][akq + 2][ar] = f2tf32(xa[i].z);
                As[nb][akq + 3][ar] = f2tf32(xa[i].w);
                int bkk = idx >> 5, bcc = (idx & 31) * 4;
                uint4 wt;
                wt.x = f2tf32(wv[i].x); wt.y = f2tf32(wv[i].y);
                wt.z = f2tf32(wv[i].z); wt.w = f2tf32(wv[i].w);
                *reinterpret_cast<uint4*>(&Bs[nb][bkk][bcc]) = wt;
            }
        }
        __syncthreads();
    }

    // ---- epilogue: +bias, scatter to [b][h][s][d] ----
    #pragma unroll
    for (int nt = 0; nt < 4; nt++) {
        const int col = col0 + wn + nt * 8 + tig * 2;
        const int h_ = col >> 6;
        const int d_ = col & 63;
        const float2 bb = *reinterpret_cast<const float2*>(&bias[col]);
        #pragma unroll
        for (int mt = 0; mt < 4; mt++) {
            int rowa = row0 + wm + mt * 16 + grp;
            #pragma unroll
            for (int half = 0; half < 2; half++) {
                int row = rowa + half * 8;
                int b_ = row >> 11;
                int s_ = row & 2047;
                float2 rv;
                rv.x = c[mt][nt][half * 2 + 0] + bb.x;
                rv.y = c[mt][nt][half * 2 + 1] + bb.y;
                *reinterpret_cast<float2*>(
                    &out[((size_t)((b_ * HH + h_) * SS) + s_) * HD + d_]) = rv;
            }
        }
    }
}

// ---------------------------------------------------------------------------
// tf32-mma flash block-sparse attention over 64-query windows.
// Grid: (window, head, batch). 128 threads = 4 warps; warp w: 16 q x 64 keys.
// Q fragments live in REGISTERS (loaded once) -> no Qs smem, fewer LDS/tile.
// Smem: KP[64][68] (K then P), Vt[64][68], kpms[64] = 35 KB.
// ---------------------------------------------------------------------------
#define PAD 68
#define SM_KP 0
#define SM_VT (64*PAD)
#define SM_KPM (2*64*PAD)
#define SM_FLOATS (2*64*PAD + 64)

__global__ void __launch_bounds__(128, 4)
sparse_attn_kernel(const float* __restrict__ kpm, float* __restrict__ out) {
    extern __shared__ float smf[];
    uint32_t* KP   = reinterpret_cast<uint32_t*>(smf + SM_KP);
    uint32_t* Vt   = reinterpret_cast<uint32_t*>(smf + SM_VT);
    float*    kpms = smf + SM_KPM;

    const int w = blockIdx.x;
    const int h = blockIdx.y;
    const int b = blockIdx.z;

    const int tid  = threadIdx.x;
    const int lane = tid & 31;
    const int warp = tid >> 5;
    const int wq   = warp * 16;
    const int grp  = lane >> 2;
    const int tig  = lane & 3;

    const size_t head_base = (size_t)(b * HH + h) * SS * HD;
    const int row_a = wq + grp;
    const int row_b = wq + grp + 8;

    // ---- Q fragments in registers (per-thread, loaded once) ----
    uint32_t qa[8][4];
    {
        const float* qra = g_q + head_base + (size_t)(w * 64 + row_a) * HD;
        const float* qrb = g_q + head_base + (size_t)(w * 64 + row_b) * HD;
        #pragma unroll
        for (int ks = 0; ks < 8; ks++) {
            qa[ks][0] = f2tf32(qra[ks * 8 + tig]);
            qa[ks][1] = f2tf32(qrb[ks * 8 + tig]);
            qa[ks][2] = f2tf32(qra[ks * 8 + tig + 4]);
            qa[ks][3] = f2tf32(qrb[ks * 8 + tig + 4]);
        }
    }

    float o[8][4];
    #pragma unroll
    for (int nt = 0; nt < 8; nt++)
        #pragma unroll
        for (int r = 0; r < 4; r++) o[nt][r] = 0.f;
    float m0 = -1e30f, m1 = -1e30f, l0 = 0.f, l1 = 0.f;

    const float scale = 0.125f;
    const int nkt = (w + 3) >> 2;

    for (int it = 0; it <= nkt; it++) {
        const bool isWin = (it == nkt);

        __syncthreads();   // prior-tile P/Vt consumers done

        // ---- Stage K natural (KP[key][d]) + V transposed (Vt[d][key]) ----
        {
            const int r  = tid >> 1;
            const int dh = (tid & 1) * 32;
            int kb; bool valid;
            if (isWin) { kb = 4 * w + (r >> 4); valid = true; }
            else {
                int g = it * 4 + (r >> 4);
                valid = (g < w);
                kb = 4 * g + 3;
            }
            const float* krow = g_k + head_base + (size_t)(kb * 16 + (r & 15)) * HD + dh;
            const float* vrow = g_v + head_base + (size_t)(kb * 16 + (r & 15)) * HD + dh;
            const float4 z4 = make_float4(0.f, 0.f, 0.f, 0.f);
            #pragma unroll
            for (int u = 0; u < 8; u++) {
                float4 kv = valid ? *reinterpret_cast<const float4*>(&krow[u * 4]) : z4;
                uint4 kt;
                kt.x = f2tf32(kv.x); kt.y = f2tf32(kv.y);
                kt.z = f2tf32(kv.z); kt.w = f2tf32(kv.w);
                *reinterpret_cast<uint4*>(&KP[r * PAD + dh + u * 4]) = kt;
                float4 vv = valid ? *reinterpret_cast<const float4*>(&vrow[u * 4]) : z4;
                Vt[(dh + u * 4 + 0) * PAD + r] = f2tf32(vv.x);
                Vt[(dh + u * 4 + 1) * PAD + r] = f2tf32(vv.y);
                Vt[(dh + u * 4 + 2) * PAD + r] = f2tf32(vv.z);
                Vt[(dh + u * 4 + 3) * PAD + r] = f2tf32(vv.w);
            }
            if (tid < 64) {
                int kk = tid;
                int kb2; bool v2;
                if (isWin) { kb2 = 4 * w + (kk >> 4); v2 = true; }
                else {
                    int g2 = it * 4 + (kk >> 4);
                    v2 = (g2 < w);
                    kb2 = 4 * g2 + 3;
                }
                kpms[kk] = v2 ? kpm[b * SS + kb2 * 16 + (kk & 15)] : -INFINITY;
            }
        }
        __syncthreads();

        // ---- S = Q K^T : warp tile 16 x 64 (8 n-tiles) ----
        float sc[8][4];
        #pragma unroll
        for (int nt = 0; nt < 8; nt++)
            #pragma unroll
            for (int r = 0; r < 4; r++) sc[nt][r] = 0.f;

        #pragma unroll
        for (int ks = 0; ks < 8; ks++) {
            #pragma unroll
            for (int nt = 0; nt < 8; nt++) {
                uint32_t bfr[2];
                bfr[0] = KP[(nt * 8 + grp) * PAD + ks * 8 + tig];
                bfr[1] = KP[(nt * 8 + grp) * PAD + ks * 8 + tig + 4];
                mma_tf32(sc[nt], qa[ks], bfr);
            }
        }

        // ---- scale + kpm + window mask ----
        #pragma unroll
        for (int nt = 0; nt < 8; nt++) {
            #pragma unroll
            for (int cc = 0; cc < 2; cc++) {
                int col = nt * 8 + tig * 2 + cc;
                float kv = kpms[col];
                float v0 = sc[nt][cc]     * scale + kv;
                float v1 = sc[nt][2 + cc] * scale + kv;
                if (isWin) {
                    if ((col >> 4) > (row_a >> 4)) v0 = -INFINITY;
                    if ((col >> 4) > (row_b >> 4)) v1 = -INFINITY;
                }
                sc[nt][cc] = v0;
                sc[nt][2 + cc] = v1;
            }
        }

        // ---- online softmax ----
        float mx0 = -INFINITY, mx1 = -INFINITY;
        #pragma unroll
        for (int nt = 0; nt < 8; nt++) {
            mx0 = fmaxf(mx0, fmaxf(sc[nt][0], sc[nt][1]));
            mx1 = fmaxf(mx1, fmaxf(sc[nt][2], sc[nt][3]));
        }
        mx0 = fmaxf(mx0, __shfl_xor_sync(0xffffffffu, mx0, 1));
        mx0 = fmaxf(mx0, __shfl_xor_sync(0xffffffffu, mx0, 2));
        mx1 = fmaxf(mx1, __shfl_xor_sync(0xffffffffu, mx1, 1));
        mx1 = fmaxf(mx1, __shfl_xor_sync(0xffffffffu, mx1, 2));

        const float nm0 = fmaxf(m0, mx0);
        const float nm1 = fmaxf(m1, mx1);
        const float al0 = __expf(m0 - nm0);
        const float al1 = __expf(m1 - nm1);
        m0 = nm0; m1 = nm1;

        float rs0 = 0.f, rs1 = 0.f;
        #pragma unroll
        for (int nt = 0; nt < 8; nt++) {
            #pragma unroll
            for (int cc = 0; cc < 2; cc++) {
                float p0 = __expf(sc[nt][cc] - nm0);
                float p1 = __expf(sc[nt][2 + cc] - nm1);
                sc[nt][cc] = p0;
                sc[nt][2 + cc] = p1;
                rs0 += p0; rs1 += p1;
            }
        }
        rs0 += __shfl_xor_sync(0xffffffffu, rs0, 1);
        rs0 += __shfl_xor_sync(0xffffffffu, rs0, 2);
        rs1 += __shfl_xor_sync(0xffffffffu, rs1, 1);
        rs1 += __shfl_xor_sync(0xffffffffu, rs1, 2);
        l0 = l0 * al0 + rs0;
        l1 = l1 * al1 + rs1;
        #pragma unroll
        for (int nt = 0; nt < 8; nt++) {
            o[nt][0] *= al0; o[nt][1] *= al0;
            o[nt][2] *= al1; o[nt][3] *= al1;
        }

        __syncthreads();   // all warps done reading K before P overwrite

        // ---- write P (tf32) into KP as [q][key] ----
        #pragma unroll
        for (int nt = 0; nt < 8; nt++) {
            uint2 p0, p1;
            p0.x = f2tf32(sc[nt][0]); p0.y = f2tf32(sc[nt][1]);
            p1.x = f2tf32(sc[nt][2]); p1.y = f2tf32(sc[nt][3]);
            *reinterpret_cast<uint2*>(&KP[row_a * PAD + nt * 8 + tig * 2]) = p0;
            *reinterpret_cast<uint2*>(&KP[row_b * PAD + nt * 8 + tig * 2]) = p1;
        }
        __syncwarp();   // P rows for this warp's PV are warp-local

        // ---- O += P V ----
        #pragma unroll
        for (int ks = 0; ks < 8; ks++) {
            uint32_t a[4];
            a[0] = KP[row_a * PAD + ks * 8 + tig];
            a[1] = KP[row_b * PAD + ks * 8 + tig];
            a[2] = KP[row_a * PAD + ks * 8 + tig + 4];
            a[3] = KP[row_b * PAD + ks * 8 + tig + 4];
            #pragma unroll
            for (int nt = 0; nt < 8; nt++) {
                uint32_t bfr[2];
                bfr[0] = Vt[(nt * 8 + grp) * PAD + ks * 8 + tig];
                bfr[1] = Vt[(nt * 8 + grp) * PAD + ks * 8 + tig + 4];
                mma_tf32(o[nt], a, bfr);
            }
        }
    }

    // ---- epilogue: normalize, write out[b][s][h*64+d] ----
    const float inv0 = 1.f / l0;
    const float inv1 = 1.f / l1;
    #pragma unroll
    for (int nt = 0; nt < 8; nt++) {
        int d_ = nt * 8 + tig * 2;
        float2 r0, r1;
        r0.x = o[nt][0] * inv0; r0.y = o[nt][1] * inv0;
        r1.x = o[nt][2] * inv1; r1.y = o[nt][3] * inv1;
        *reinterpret_cast<float2*>(
            &out[(size_t)(b * SS + w * 64 + row_a) * DD + h * HD + d_]) = r0;
        *reinterpret_cast<float2*>(
            &out[(size_t)(b * SS + w * 64 + row_b) * DD + h * HD + d_]) = r1;
    }
}

// ---------------------------------------------------------------------------
// Launch
// ---------------------------------------------------------------------------
extern "C" void kernel_launch(void* const* d_in, const int* in_sizes, int n_in,
                              void* d_out, int out_size) {
    const float* x   = (const float*)d_in[0];
    const float* kpm = (const float*)d_in[1];
    const float* Wq  = (const float*)d_in[2];
    const float* bq  = (const float*)d_in[3];
    const float* Wk  = (const float*)d_in[4];
    const float* bk  = (const float*)d_in[5];
    const float* Wv  = (const float*)d_in[6];
    const float* bv  = (const float*)d_in[7];
    float* out = (float*)d_out;

    dim3 ggrid(32, 8, 3);
    qkv_gemm_tf32<<<ggrid, 256>>>(x, Wq, bq, Wk, bk, Wv, bv);

    static int smem_set = 0;
    const int smem_bytes = SM_FLOATS * sizeof(float);   // 35072
    if (!smem_set) {
        cudaFuncSetAttribute(sparse_attn_kernel,
                             cudaFuncAttributeMaxDynamicSharedMemorySize,
                             smem_bytes);
        smem_set = 1;
    }
    dim3 agrid(32, HH, BB);
    sparse_attn_kernel<<<agrid, 128, smem_bytes>>>(kpm, out);
}